// round 1
// baseline (speedup 1.0000x reference)
#include <cuda_runtime.h>
#include <cstdint>

// Problem shapes (fixed by the dataset)
#define S_DIM 1024
#define B_DIM 2
#define T_DIM 2048          // S*B tokens
#define H_DIM 1024
#define E_DIM 8
#define FFN_DIM 1408
#define FFN2_DIM 2816       // 2*FFN
#define NPAIR 4096          // T * TOP_K

// ---------------- scratch (device globals; no dynamic alloc allowed) -------
__device__ int   g_topk_idx[T_DIM * 2];
__device__ float g_topk_w[T_DIM * 2];
__device__ int   g_tok[NPAIR];          // compact pair -> token
__device__ int   g_slot[T_DIM * 2];     // (t,k) -> compact pair row
__device__ int   g_base[E_DIM];
__device__ int   g_cnt[E_DIM];
__device__ float g_act[(size_t)NPAIR * FFN_DIM];   // ~23 MB
__device__ float g_y[(size_t)NPAIR * H_DIM];       // ~16.8 MB

// ---------------- gate: softmax(x @ gate_w^T), top-2, renormalize ----------
__global__ void __launch_bounds__(256) gate_kernel(
    const float* __restrict__ x, const float* __restrict__ gw)
{
    int t = blockIdx.x;
    const float* xr = x + (size_t)t * H_DIM;
    int wid = threadIdx.x >> 5, lane = threadIdx.x & 31;
    __shared__ float sc[E_DIM];

    const float* g = gw + (size_t)wid * H_DIM;
    float s = 0.f;
    for (int i = lane; i < H_DIM; i += 32) s += xr[i] * g[i];
#pragma unroll
    for (int o = 16; o; o >>= 1) s += __shfl_xor_sync(0xffffffffu, s, o);
    if (lane == 0) sc[wid] = s;
    __syncthreads();

    if (threadIdx.x == 0) {
        float m = -1e30f;
#pragma unroll
        for (int e = 0; e < E_DIM; e++) m = fmaxf(m, sc[e]);
        float p[E_DIM], den = 0.f;
#pragma unroll
        for (int e = 0; e < E_DIM; e++) { p[e] = __expf(sc[e] - m); den += p[e]; }
        int i0 = 0;
#pragma unroll
        for (int e = 1; e < E_DIM; e++) if (p[e] > p[i0]) i0 = e;
        int i1 = -1;
#pragma unroll
        for (int e = 0; e < E_DIM; e++)
            if (e != i0 && (i1 < 0 || p[e] > p[i1])) i1 = e;
        float q0 = p[i0] / den, q1 = p[i1] / den;
        float wsum = q0 + q1 + 1e-20f;
        g_topk_idx[2 * t]     = i0;
        g_topk_idx[2 * t + 1] = i1;
        g_topk_w[2 * t]       = q0 / wsum;
        g_topk_w[2 * t + 1]   = q1 / wsum;
    }
}

// ---------------- scatter: deterministic compaction by expert --------------
// One block, 8 warps; warp e owns expert e. No atomics.
__global__ void __launch_bounds__(256) scatter_kernel()
{
    int wid = threadIdx.x >> 5, lane = threadIdx.x & 31;
    __shared__ int scnt[E_DIM];

    // pass 1: count
    int c = 0;
    for (int baset = 0; baset < T_DIM; baset += 32) {
        int t = baset + lane;
        bool m = (g_topk_idx[2 * t] == wid) || (g_topk_idx[2 * t + 1] == wid);
        unsigned b = __ballot_sync(0xffffffffu, m);
        c += __popc(b);
    }
    if (lane == 0) scnt[wid] = c;
    __syncthreads();
    if (threadIdx.x == 0) {
        int acc = 0;
        for (int e = 0; e < E_DIM; e++) { g_base[e] = acc; g_cnt[e] = scnt[e]; acc += scnt[e]; }
    }
    __syncthreads();

    // pass 2: stable append
    int pos = g_base[wid];
    for (int baset = 0; baset < T_DIM; baset += 32) {
        int t = baset + lane;
        int k = -1;
        if (g_topk_idx[2 * t] == wid) k = 0;
        else if (g_topk_idx[2 * t + 1] == wid) k = 1;
        unsigned b = __ballot_sync(0xffffffffu, k >= 0);
        int off = __popc(b & ((1u << lane) - 1u));
        if (k >= 0) {
            g_tok[pos + off] = t;
            g_slot[2 * t + k] = pos + off;
        }
        pos += __popc(b);
    }
}

// ---------------- grouped GEMM1 (X_e @ w1[e]) + fused swiglu ---------------
// 64x64 tile, BK=16, 256 threads, each thread 4x4 for g-half and u-half.
__global__ void __launch_bounds__(256) gemm1_kernel(
    const float* __restrict__ x, const float* __restrict__ w1)
{
    int e = blockIdx.z;
    int cnt = g_cnt[e];
    int m0 = blockIdx.y * 64;
    if (m0 >= cnt) return;
    int n0 = blockIdx.x * 64;       // 22 tiles cover 1408
    int base = g_base[e];

    __shared__ float As[16][64];
    __shared__ float Bg[16][64];
    __shared__ float Bu[16][64];
    __shared__ int   stok[64];

    int tid = threadIdx.x;
    if (tid < 64) {
        int r = m0 + tid;
        stok[tid] = g_tok[base + ((r < cnt) ? r : 0)];
    }
    __syncthreads();

    const int a_row = tid >> 2;          // 0..63
    const int a_k4  = (tid & 3) * 4;     // 0,4,8,12
    const int b_kk  = tid >> 4;          // 0..15
    const int b_n   = (tid & 15) * 4;    // 0..60

    const float* xrow = x + (size_t)stok[a_row] * H_DIM;
    const float* wg_base = w1 + (size_t)e * H_DIM * FFN2_DIM + n0 + b_n;

    const int ty = tid >> 4, tx = tid & 15;
    float accg[4][4] = {}, accu[4][4] = {};

    for (int k0 = 0; k0 < H_DIM; k0 += 16) {
        float4 av = *(const float4*)(xrow + k0 + a_k4);
        As[a_k4 + 0][a_row] = av.x;
        As[a_k4 + 1][a_row] = av.y;
        As[a_k4 + 2][a_row] = av.z;
        As[a_k4 + 3][a_row] = av.w;
        const float* wrow = wg_base + (size_t)(k0 + b_kk) * FFN2_DIM;
        float4 bgv = *(const float4*)(wrow);
        float4 buv = *(const float4*)(wrow + FFN_DIM);
        *(float4*)&Bg[b_kk][b_n] = bgv;
        *(float4*)&Bu[b_kk][b_n] = buv;
        __syncthreads();
#pragma unroll
        for (int kk = 0; kk < 16; kk++) {
            float4 a  = *(const float4*)&As[kk][ty * 4];
            float4 bg = *(const float4*)&Bg[kk][tx * 4];
            float4 bu = *(const float4*)&Bu[kk][tx * 4];
            float aa[4] = {a.x, a.y, a.z, a.w};
            float gg[4] = {bg.x, bg.y, bg.z, bg.w};
            float uu[4] = {bu.x, bu.y, bu.z, bu.w};
#pragma unroll
            for (int i = 0; i < 4; i++)
#pragma unroll
                for (int j = 0; j < 4; j++) {
                    accg[i][j] += aa[i] * gg[j];
                    accu[i][j] += aa[i] * uu[j];
                }
        }
        __syncthreads();
    }

#pragma unroll
    for (int i = 0; i < 4; i++) {
        int row = m0 + ty * 4 + i;
        if (row < cnt) {
            float4 o;
            float* op = (float*)&o;
#pragma unroll
            for (int j = 0; j < 4; j++) {
                float gv = accg[i][j];
                float uv = accu[i][j];
                op[j] = gv * uv / (1.f + __expf(-gv));   // silu(g)*u
            }
            *(float4*)&g_act[(size_t)(base + row) * FFN_DIM + n0 + tx * 4] = o;
        }
    }
}

// ---------------- grouped GEMM2 (act_e @ w2[e]) -> Y -----------------------
__global__ void __launch_bounds__(256) gemm2_kernel(const float* __restrict__ w2)
{
    int e = blockIdx.z;
    int cnt = g_cnt[e];
    int m0 = blockIdx.y * 64;
    if (m0 >= cnt) return;
    int n0 = blockIdx.x * 64;       // 16 tiles cover 1024
    int base = g_base[e];

    __shared__ float As[16][64];
    __shared__ float Bs[16][64];

    int tid = threadIdx.x;
    const int a_row = tid >> 2;
    const int a_k4  = (tid & 3) * 4;
    const int b_kk  = tid >> 4;
    const int b_n   = (tid & 15) * 4;

    int arow_g = base + m0 + a_row;
    if (arow_g > NPAIR - 1) arow_g = NPAIR - 1;   // clamp OOB (guarded at store)
    const float* arow = g_act + (size_t)arow_g * FFN_DIM;
    const float* wb = w2 + (size_t)e * FFN_DIM * H_DIM + n0 + b_n;

    const int ty = tid >> 4, tx = tid & 15;
    float acc[4][4] = {};

    for (int k0 = 0; k0 < FFN_DIM; k0 += 16) {
        float4 av = *(const float4*)(arow + k0 + a_k4);
        As[a_k4 + 0][a_row] = av.x;
        As[a_k4 + 1][a_row] = av.y;
        As[a_k4 + 2][a_row] = av.z;
        As[a_k4 + 3][a_row] = av.w;
        *(float4*)&Bs[b_kk][b_n] = *(const float4*)(wb + (size_t)(k0 + b_kk) * H_DIM);
        __syncthreads();
#pragma unroll
        for (int kk = 0; kk < 16; kk++) {
            float4 a = *(const float4*)&As[kk][ty * 4];
            float4 b = *(const float4*)&Bs[kk][tx * 4];
            float aa[4] = {a.x, a.y, a.z, a.w};
            float bb[4] = {b.x, b.y, b.z, b.w};
#pragma unroll
            for (int i = 0; i < 4; i++)
#pragma unroll
                for (int j = 0; j < 4; j++)
                    acc[i][j] += aa[i] * bb[j];
        }
        __syncthreads();
    }

#pragma unroll
    for (int i = 0; i < 4; i++) {
        int row = m0 + ty * 4 + i;
        if (row < cnt) {
            float4 o = make_float4(acc[i][0], acc[i][1], acc[i][2], acc[i][3]);
            *(float4*)&g_y[(size_t)(base + row) * H_DIM + n0 + tx * 4] = o;
        }
    }
}

// ---------------- combine: out[t] = w0*Y[slot0] + w1*Y[slot1] --------------
__global__ void __launch_bounds__(256) combine_kernel(float* __restrict__ out)
{
    int t = blockIdx.x;
    int s0 = g_slot[2 * t], s1 = g_slot[2 * t + 1];
    float w0 = g_topk_w[2 * t], w1 = g_topk_w[2 * t + 1];
    const float* y0 = g_y + (size_t)s0 * H_DIM;
    const float* y1 = g_y + (size_t)s1 * H_DIM;
    float* orow = out + (size_t)t * H_DIM;

    int h = threadIdx.x * 4;   // 256 threads * 4 = 1024 = H
    float4 a = *(const float4*)(y0 + h);
    float4 b = *(const float4*)(y1 + h);
    float4 o;
    o.x = w0 * a.x + w1 * b.x;
    o.y = w0 * a.y + w1 * b.y;
    o.z = w0 * a.z + w1 * b.z;
    o.w = w0 * a.w + w1 * b.w;
    *(float4*)(orow + h) = o;
}

// ---------------- launch ----------------------------------------------------
extern "C" void kernel_launch(void* const* d_in, const int* in_sizes, int n_in,
                              void* d_out, int out_size)
{
    const float* hidden = (const float*)d_in[0];   // [S, B, H]
    const float* gate_w = (const float*)d_in[1];   // [E, H]
    const float* w1     = (const float*)d_in[2];   // [E, H, 2*FFN]
    const float* w2     = (const float*)d_in[3];   // [E, FFN, H]
    float* out          = (float*)d_out;           // [S, B, H]

    // Token t = row t of hidden flattened [S*B, H]; the two transposes in the
    // reference cancel per-token, so out row t = f(hidden row t).
    gate_kernel<<<T_DIM, 256>>>(hidden, gate_w);
    scatter_kernel<<<1, 256>>>();
    gemm1_kernel<<<dim3(FFN_DIM / 64, T_DIM / 64, E_DIM), 256>>>(hidden, w1);
    gemm2_kernel<<<dim3(H_DIM / 64, T_DIM / 64, E_DIM), 256>>>(w2);
    combine_kernel<<<T_DIM, 256>>>(out);
}

// round 3
// speedup vs baseline: 1.8126x; 1.8126x over previous
#include <cuda_runtime.h>
#include <cstdint>

// Problem shapes (fixed by the dataset)
#define T_DIM 2048
#define H_DIM 1024
#define E_DIM 8
#define FFN_DIM 1408
#define FFN2_DIM 2816
#define NPAIR 4096
#define NPAD (NPAIR + 128)

// ---------------- scratch (device globals) ----------------------------------
__device__ int   g_topk_idx[T_DIM * 2];
__device__ float g_topk_w[T_DIM * 2];
__device__ int   g_tok[NPAIR];
__device__ int   g_slot[T_DIM * 2];
__device__ int   g_base[E_DIM];
__device__ int   g_cnt[E_DIM];
__device__ float g_act[(size_t)NPAD * FFN_DIM];   // swiglu output
__device__ float g_y[(size_t)NPAIR * H_DIM];      // expert outputs

// ---------------- helpers ----------------------------------------------------
__device__ __forceinline__ float rtf32(float x) {
    uint32_t u;
    asm("cvt.rna.tf32.f32 %0, %1;" : "=r"(u) : "f"(x));
    return __uint_as_float(u);
}
__device__ __forceinline__ void mma_tf32(float* c,
                                         uint32_t a0, uint32_t a1, uint32_t a2, uint32_t a3,
                                         uint32_t b0, uint32_t b1) {
    asm volatile(
        "mma.sync.aligned.m16n8k8.row.col.f32.tf32.tf32.f32 "
        "{%0,%1,%2,%3}, {%4,%5,%6,%7}, {%8,%9}, {%0,%1,%2,%3};"
        : "+f"(c[0]), "+f"(c[1]), "+f"(c[2]), "+f"(c[3])
        : "r"(a0), "r"(a1), "r"(a2), "r"(a3), "r"(b0), "r"(b1));
}

// smem: double-buffered A[2][128][36], B[2][128][36] floats
#define PITCH 36
#define BUFSZ (128 * PITCH)
#define SMEM_BYTES (4 * BUFSZ * 4)   // 73728
#define SA(buf, r, c) sm[(buf) * BUFSZ + (r) * PITCH + (c)]
#define SB(buf, r, c) sm[2 * BUFSZ + (buf) * BUFSZ + (r) * PITCH + (c)]

// ---------------- gate: softmax(x @ gate_w^T), top-2, renormalize ----------
__global__ void __launch_bounds__(256) gate_kernel(
    const float* __restrict__ x, const float* __restrict__ gw)
{
    int t = blockIdx.x;
    const float* xr = x + (size_t)t * H_DIM;
    int wid = threadIdx.x >> 5, lane = threadIdx.x & 31;
    __shared__ float sc[E_DIM];

    const float* g = gw + (size_t)wid * H_DIM;
    float s = 0.f;
    for (int i = lane; i < H_DIM; i += 32) s += xr[i] * g[i];
#pragma unroll
    for (int o = 16; o; o >>= 1) s += __shfl_xor_sync(0xffffffffu, s, o);
    if (lane == 0) sc[wid] = s;
    __syncthreads();

    if (threadIdx.x == 0) {
        float m = -1e30f;
#pragma unroll
        for (int e = 0; e < E_DIM; e++) m = fmaxf(m, sc[e]);
        float p[E_DIM], den = 0.f;
#pragma unroll
        for (int e = 0; e < E_DIM; e++) { p[e] = __expf(sc[e] - m); den += p[e]; }
        int i0 = 0;
#pragma unroll
        for (int e = 1; e < E_DIM; e++) if (p[e] > p[i0]) i0 = e;
        int i1 = -1;
#pragma unroll
        for (int e = 0; e < E_DIM; e++)
            if (e != i0 && (i1 < 0 || p[e] > p[i1])) i1 = e;
        float q0 = p[i0] / den, q1 = p[i1] / den;
        float wsum = q0 + q1 + 1e-20f;
        g_topk_idx[2 * t]     = i0;
        g_topk_idx[2 * t + 1] = i1;
        g_topk_w[2 * t]       = q0 / wsum;
        g_topk_w[2 * t + 1]   = q1 / wsum;
    }
}

// ---------------- scatter: deterministic compaction by expert --------------
__global__ void __launch_bounds__(256) scatter_kernel()
{
    int wid = threadIdx.x >> 5, lane = threadIdx.x & 31;
    __shared__ int scnt[E_DIM];

    int c = 0;
    for (int baset = 0; baset < T_DIM; baset += 32) {
        int t = baset + lane;
        bool m = (g_topk_idx[2 * t] == wid) || (g_topk_idx[2 * t + 1] == wid);
        unsigned b = __ballot_sync(0xffffffffu, m);
        c += __popc(b);
    }
    if (lane == 0) scnt[wid] = c;
    __syncthreads();
    if (threadIdx.x == 0) {
        int acc = 0;
        for (int e = 0; e < E_DIM; e++) { g_base[e] = acc; g_cnt[e] = scnt[e]; acc += scnt[e]; }
    }
    __syncthreads();

    int pos = g_base[wid];
    for (int baset = 0; baset < T_DIM; baset += 32) {
        int t = baset + lane;
        int k = -1;
        if (g_topk_idx[2 * t] == wid) k = 0;
        else if (g_topk_idx[2 * t + 1] == wid) k = 1;
        unsigned b = __ballot_sync(0xffffffffu, k >= 0);
        int off = __popc(b & ((1u << lane) - 1u));
        if (k >= 0) {
            g_tok[pos + off] = t;
            g_slot[2 * t + k] = pos + off;
        }
        pos += __popc(b);
    }
}

// ---------------- GEMM1: gathered X[128,1024] @ w1 -> swiglu -> g_act -------
// Block: 128 pair-rows x 64 FFN cols (gate half in B rows 0-63, up in 64-127).
__global__ void __launch_bounds__(256) gemm1_kernel(
    const float* __restrict__ x, const float* __restrict__ w1)
{
    int e = blockIdx.z;
    int cnt = g_cnt[e];
    int m0 = blockIdx.y * 128;
    if (m0 >= cnt) return;
    int base = g_base[e];
    int n0 = blockIdx.x * 64;

    extern __shared__ float sm[];
    __shared__ int stok[128];
    int tid = threadIdx.x;
    if (tid < 128) {
        int r = m0 + tid;
        stok[tid] = g_tok[base + ((r < cnt) ? r : (cnt - 1))];
    }
    __syncthreads();

    const float* w1e = w1 + (size_t)e * ((size_t)H_DIM * FFN2_DIM);

    // Per-thread global/smem coords (fixed across K stages)
    const float* aptr[4];
    const float* bptr[4];
    int aoff[4], bn4[4], bk[4];
#pragma unroll
    for (int i = 0; i < 4; i++) {
        int idx = tid + (i << 8);
        int r = idx >> 3, q = idx & 7;               // A: 128 rows x 8 float4
        aptr[i] = x + (size_t)stok[r] * H_DIM + q * 4;
        aoff[i] = r * PITCH + q * 4;
        int k = idx >> 5, n4 = (idx & 31) * 4;       // B: 32 k x 32 n-quads
        int col = (n4 < 64) ? (n0 + n4) : (FFN_DIM + n0 + (n4 - 64));
        bptr[i] = w1e + (size_t)k * FFN2_DIM + col;
        bn4[i] = n4; bk[i] = k;
    }

    float4 av[4], bv[4];
#pragma unroll
    for (int i = 0; i < 4; i++) { av[i] = *(const float4*)aptr[i]; bv[i] = *(const float4*)bptr[i]; }
#pragma unroll
    for (int i = 0; i < 4; i++) {
        float4 v = av[i];
        v.x = rtf32(v.x); v.y = rtf32(v.y); v.z = rtf32(v.z); v.w = rtf32(v.w);
        *(float4*)&SA(0, 0, aoff[i]) = v;
        float4 w = bv[i];
        SB(0, bn4[i] + 0, bk[i]) = rtf32(w.x);
        SB(0, bn4[i] + 1, bk[i]) = rtf32(w.y);
        SB(0, bn4[i] + 2, bk[i]) = rtf32(w.z);
        SB(0, bn4[i] + 3, bk[i]) = rtf32(w.w);
    }
    __syncthreads();

    int lane = tid & 31, wid = tid >> 5;
    int gid = lane >> 2, tig = lane & 3;
    int wm = wid >> 2, wn = wid & 3;

    float acc[4][4][4] = {};   // [mtile][jtile: 0,1 gate / 2,3 up][frag]

    const int NS = H_DIM / 32;
    for (int s = 0; s < NS; s++) {
        int b = s & 1;
        if (s + 1 < NS) {
            int k0 = (s + 1) * 32;
#pragma unroll
            for (int i = 0; i < 4; i++) {
                av[i] = *(const float4*)(aptr[i] + k0);
                bv[i] = *(const float4*)(bptr[i] + (size_t)k0 * FFN2_DIM);
            }
        }
#pragma unroll
        for (int kk = 0; kk < 4; kk++) {
            int kq = kk * 8 + tig;
            uint32_t bf[4][2];
#pragma unroll
            for (int j = 0; j < 4; j++) {
                int nrow = ((j < 2) ? (wn * 16 + j * 8) : (64 + wn * 16 + (j - 2) * 8)) + gid;
                bf[j][0] = __float_as_uint(SB(b, nrow, kq));
                bf[j][1] = __float_as_uint(SB(b, nrow, kq + 4));
            }
#pragma unroll
            for (int mt = 0; mt < 4; mt++) {
                int ar = wm * 64 + mt * 16 + gid;
                uint32_t a0 = __float_as_uint(SA(b, ar, kq));
                uint32_t a1 = __float_as_uint(SA(b, ar + 8, kq));
                uint32_t a2 = __float_as_uint(SA(b, ar, kq + 4));
                uint32_t a3 = __float_as_uint(SA(b, ar + 8, kq + 4));
#pragma unroll
                for (int j = 0; j < 4; j++)
                    mma_tf32(acc[mt][j], a0, a1, a2, a3, bf[j][0], bf[j][1]);
            }
        }
        if (s + 1 < NS) {
            int nb = b ^ 1;
#pragma unroll
            for (int i = 0; i < 4; i++) {
                float4 v = av[i];
                v.x = rtf32(v.x); v.y = rtf32(v.y); v.z = rtf32(v.z); v.w = rtf32(v.w);
                *(float4*)&SA(nb, 0, aoff[i]) = v;
                float4 w = bv[i];
                SB(nb, bn4[i] + 0, bk[i]) = rtf32(w.x);
                SB(nb, bn4[i] + 1, bk[i]) = rtf32(w.y);
                SB(nb, bn4[i] + 2, bk[i]) = rtf32(w.z);
                SB(nb, bn4[i] + 3, bk[i]) = rtf32(w.w);
            }
        }
        __syncthreads();
    }

    // epilogue: swiglu(g,u) -> g_act
#pragma unroll
    for (int mt = 0; mt < 4; mt++) {
        int rr = m0 + wm * 64 + mt * 16 + gid;
#pragma unroll
        for (int p = 0; p < 2; p++) {
            int col = n0 + wn * 16 + p * 8 + tig * 2;
            if (rr < cnt) {
                float g0 = acc[mt][p][0], u0 = acc[mt][p + 2][0];
                float g1 = acc[mt][p][1], u1 = acc[mt][p + 2][1];
                float2 o;
                o.x = g0 * u0 / (1.f + __expf(-g0));
                o.y = g1 * u1 / (1.f + __expf(-g1));
                *(float2*)&g_act[(size_t)(base + rr) * FFN_DIM + col] = o;
            }
            if (rr + 8 < cnt) {
                float g0 = acc[mt][p][2], u0 = acc[mt][p + 2][2];
                float g1 = acc[mt][p][3], u1 = acc[mt][p + 2][3];
                float2 o;
                o.x = g0 * u0 / (1.f + __expf(-g0));
                o.y = g1 * u1 / (1.f + __expf(-g1));
                *(float2*)&g_act[(size_t)(base + rr + 8) * FFN_DIM + col] = o;
            }
        }
    }
}

// ---------------- GEMM2: g_act[128,1408] @ w2 -> g_y -----------------------
__global__ void __launch_bounds__(256) gemm2_kernel(const float* __restrict__ w2)
{
    int e = blockIdx.z;
    int cnt = g_cnt[e];
    int m0 = blockIdx.y * 128;
    if (m0 >= cnt) return;
    int base = g_base[e];
    int n0 = blockIdx.x * 128;

    extern __shared__ float sm[];
    int tid = threadIdx.x;

    const float* Ab  = g_act + (size_t)(base + m0) * FFN_DIM;
    const float* w2e = w2 + (size_t)e * ((size_t)FFN_DIM * H_DIM);

    const float* aptr[4];
    const float* bptr[4];
    int aoff[4], bn4[4], bk[4];
#pragma unroll
    for (int i = 0; i < 4; i++) {
        int idx = tid + (i << 8);
        int r = idx >> 3, q = idx & 7;
        aptr[i] = Ab + (size_t)r * FFN_DIM + q * 4;
        aoff[i] = r * PITCH + q * 4;
        int k = idx >> 5, n4 = (idx & 31) * 4;
        bptr[i] = w2e + (size_t)k * H_DIM + n0 + n4;
        bn4[i] = n4; bk[i] = k;
    }

    float4 av[4], bv[4];
#pragma unroll
    for (int i = 0; i < 4; i++) { av[i] = *(const float4*)aptr[i]; bv[i] = *(const float4*)bptr[i]; }
#pragma unroll
    for (int i = 0; i < 4; i++) {
        float4 v = av[i];
        v.x = rtf32(v.x); v.y = rtf32(v.y); v.z = rtf32(v.z); v.w = rtf32(v.w);
        *(float4*)&SA(0, 0, aoff[i]) = v;
        float4 w = bv[i];
        SB(0, bn4[i] + 0, bk[i]) = rtf32(w.x);
        SB(0, bn4[i] + 1, bk[i]) = rtf32(w.y);
        SB(0, bn4[i] + 2, bk[i]) = rtf32(w.z);
        SB(0, bn4[i] + 3, bk[i]) = rtf32(w.w);
    }
    __syncthreads();

    int lane = tid & 31, wid = tid >> 5;
    int gid = lane >> 2, tig = lane & 3;
    int wm = wid >> 2, wn = wid & 3;

    float acc[4][4][4] = {};

    const int NS = FFN_DIM / 32;   // 44
    for (int s = 0; s < NS; s++) {
        int b = s & 1;
        if (s + 1 < NS) {
            int k0 = (s + 1) * 32;
#pragma unroll
            for (int i = 0; i < 4; i++) {
                av[i] = *(const float4*)(aptr[i] + k0);
                bv[i] = *(const float4*)(bptr[i] + (size_t)k0 * H_DIM);
            }
        }
#pragma unroll
        for (int kk = 0; kk < 4; kk++) {
            int kq = kk * 8 + tig;
            uint32_t bf[4][2];
#pragma unroll
            for (int j = 0; j < 4; j++) {
                int nrow = wn * 32 + j * 8 + gid;
                bf[j][0] = __float_as_uint(SB(b, nrow, kq));
                bf[j][1] = __float_as_uint(SB(b, nrow, kq + 4));
            }
#pragma unroll
            for (int mt = 0; mt < 4; mt++) {
                int ar = wm * 64 + mt * 16 + gid;
                uint32_t a0 = __float_as_uint(SA(b, ar, kq));
                uint32_t a1 = __float_as_uint(SA(b, ar + 8, kq));
                uint32_t a2 = __float_as_uint(SA(b, ar, kq + 4));
                uint32_t a3 = __float_as_uint(SA(b, ar + 8, kq + 4));
#pragma unroll
                for (int j = 0; j < 4; j++)
                    mma_tf32(acc[mt][j], a0, a1, a2, a3, bf[j][0], bf[j][1]);
            }
        }
        if (s + 1 < NS) {
            int nb = b ^ 1;
#pragma unroll
            for (int i = 0; i < 4; i++) {
                float4 v = av[i];
                v.x = rtf32(v.x); v.y = rtf32(v.y); v.z = rtf32(v.z); v.w = rtf32(v.w);
                *(float4*)&SA(nb, 0, aoff[i]) = v;
                float4 w = bv[i];
                SB(nb, bn4[i] + 0, bk[i]) = rtf32(w.x);
                SB(nb, bn4[i] + 1, bk[i]) = rtf32(w.y);
                SB(nb, bn4[i] + 2, bk[i]) = rtf32(w.z);
                SB(nb, bn4[i] + 3, bk[i]) = rtf32(w.w);
            }
        }
        __syncthreads();
    }

#pragma unroll
    for (int mt = 0; mt < 4; mt++) {
        int rr = m0 + wm * 64 + mt * 16 + gid;
#pragma unroll
        for (int j = 0; j < 4; j++) {
            int col = n0 + wn * 32 + j * 8 + tig * 2;
            if (rr < cnt) {
                float2 o = make_float2(acc[mt][j][0], acc[mt][j][1]);
                *(float2*)&g_y[(size_t)(base + rr) * H_DIM + col] = o;
            }
            if (rr + 8 < cnt) {
                float2 o = make_float2(acc[mt][j][2], acc[mt][j][3]);
                *(float2*)&g_y[(size_t)(base + rr + 8) * H_DIM + col] = o;
            }
        }
    }
}

// ---------------- combine: out[t] = w0*Y[slot0] + w1*Y[slot1] --------------
__global__ void __launch_bounds__(256) combine_kernel(float* __restrict__ out)
{
    int t = blockIdx.x;
    int s0 = g_slot[2 * t], s1 = g_slot[2 * t + 1];
    float w0 = g_topk_w[2 * t], w1 = g_topk_w[2 * t + 1];
    const float* y0 = g_y + (size_t)s0 * H_DIM;
    const float* y1 = g_y + (size_t)s1 * H_DIM;
    float* orow = out + (size_t)t * H_DIM;

    int h = threadIdx.x * 4;
    float4 a = *(const float4*)(y0 + h);
    float4 b = *(const float4*)(y1 + h);
    float4 o;
    o.x = w0 * a.x + w1 * b.x;
    o.y = w0 * a.y + w1 * b.y;
    o.z = w0 * a.z + w1 * b.z;
    o.w = w0 * a.w + w1 * b.w;
    *(float4*)(orow + h) = o;
}

// ---------------- launch ----------------------------------------------------
extern "C" void kernel_launch(void* const* d_in, const int* in_sizes, int n_in,
                              void* d_out, int out_size)
{
    const float* hidden = (const float*)d_in[0];   // [S, B, H] == [T, H]
    const float* gate_w = (const float*)d_in[1];   // [E, H]
    const float* w1     = (const float*)d_in[2];   // [E, H, 2*FFN]
    const float* w2     = (const float*)d_in[3];   // [E, FFN, H]
    float* out          = (float*)d_out;

    cudaFuncSetAttribute(gemm1_kernel, cudaFuncAttributeMaxDynamicSharedMemorySize, SMEM_BYTES);
    cudaFuncSetAttribute(gemm2_kernel, cudaFuncAttributeMaxDynamicSharedMemorySize, SMEM_BYTES);

    gate_kernel<<<T_DIM, 256>>>(hidden, gate_w);
    scatter_kernel<<<1, 256>>>();
    gemm1_kernel<<<dim3(FFN_DIM / 64, NPAIR / 128, E_DIM), 256, SMEM_BYTES>>>(hidden, w1);
    gemm2_kernel<<<dim3(H_DIM / 128, NPAIR / 128, E_DIM), 256, SMEM_BYTES>>>(w2);
    combine_kernel<<<T_DIM, 256>>>(out);
}

// round 4
// speedup vs baseline: 3.1395x; 1.7320x over previous
#include <cuda_runtime.h>
#include <cuda_fp16.h>
#include <cstdint>

// Problem shapes (fixed by the dataset)
#define T_DIM 2048
#define H_DIM 1024
#define E_DIM 8
#define FFN_DIM 1408
#define FFN2_DIM 2816
#define NPAIR 4096
#define NPAD (NPAIR + 128)

// ---------------- scratch (device globals) ----------------------------------
__device__ int   g_topk_idx[T_DIM * 2];
__device__ float g_topk_w[T_DIM * 2];
__device__ int   g_tok[NPAIR];
__device__ int   g_slot[T_DIM * 2];
__device__ int   g_base[E_DIM];
__device__ int   g_cnt[E_DIM];
__device__ __align__(16) __half g_xh[(size_t)NPAD * H_DIM];                // gathered tokens (half)
__device__ __align__(16) __half g_acth[(size_t)NPAD * FFN_DIM];            // swiglu out (half)
__device__ __align__(16) float  g_y[(size_t)NPAIR * H_DIM];                // expert outputs
__device__ __align__(16) __half g_w1h[(size_t)E_DIM * FFN2_DIM * H_DIM];   // w1^T half [E][2FFN][H]
__device__ __align__(16) __half g_w2h[(size_t)E_DIM * H_DIM * FFN_DIM];    // w2^T half [E][H][FFN]

// ---------------- helpers ----------------------------------------------------
__device__ __forceinline__ uint32_t smem_u32(const void* p) {
    uint32_t a;
    asm("{ .reg .u64 t; cvta.to.shared.u64 t, %1; cvt.u32.u64 %0, t; }"
        : "=r"(a) : "l"(p));
    return a;
}
__device__ __forceinline__ void cpa16(uint32_t dst, const void* src) {
    asm volatile("cp.async.cg.shared.global [%0], [%1], 16;" :: "r"(dst), "l"(src));
}
#define CPCOMMIT() asm volatile("cp.async.commit_group;" ::: "memory")
#define CPWAIT1()  asm volatile("cp.async.wait_group 1;" ::: "memory")

__device__ __forceinline__ void ldm4(uint32_t* f, uint32_t a) {
    asm volatile("ldmatrix.sync.aligned.m8n8.x4.shared.b16 {%0,%1,%2,%3}, [%4];"
                 : "=r"(f[0]), "=r"(f[1]), "=r"(f[2]), "=r"(f[3]) : "r"(a));
}
__device__ __forceinline__ void mma16(float* c, const uint32_t* a,
                                      uint32_t b0, uint32_t b1) {
    asm volatile(
        "mma.sync.aligned.m16n8k16.row.col.f32.f16.f16.f32 "
        "{%0,%1,%2,%3}, {%4,%5,%6,%7}, {%8,%9}, {%0,%1,%2,%3};"
        : "+f"(c[0]), "+f"(c[1]), "+f"(c[2]), "+f"(c[3])
        : "r"(a[0]), "r"(a[1]), "r"(a[2]), "r"(a[3]), "r"(b0), "r"(b1));
}

#define STAGE_BYTES 49152u   // A 16KB + B 32KB
#define SMEM_BYTES  (3u * STAGE_BYTES)

// ---------------- gate: softmax(x @ gate_w^T), top-2, renormalize ----------
__global__ void __launch_bounds__(256) gate_kernel(
    const float* __restrict__ x, const float* __restrict__ gw)
{
    int t = blockIdx.x;
    const float* xr = x + (size_t)t * H_DIM;
    int wid = threadIdx.x >> 5, lane = threadIdx.x & 31;
    __shared__ float sc[E_DIM];

    const float* g = gw + (size_t)wid * H_DIM;
    float s = 0.f;
    for (int i = lane; i < H_DIM; i += 32) s += xr[i] * g[i];
#pragma unroll
    for (int o = 16; o; o >>= 1) s += __shfl_xor_sync(0xffffffffu, s, o);
    if (lane == 0) sc[wid] = s;
    __syncthreads();

    if (threadIdx.x == 0) {
        float m = -1e30f;
#pragma unroll
        for (int e = 0; e < E_DIM; e++) m = fmaxf(m, sc[e]);
        float p[E_DIM], den = 0.f;
#pragma unroll
        for (int e = 0; e < E_DIM; e++) { p[e] = __expf(sc[e] - m); den += p[e]; }
        int i0 = 0;
#pragma unroll
        for (int e = 1; e < E_DIM; e++) if (p[e] > p[i0]) i0 = e;
        int i1 = -1;
#pragma unroll
        for (int e = 0; e < E_DIM; e++)
            if (e != i0 && (i1 < 0 || p[e] > p[i1])) i1 = e;
        float q0 = p[i0] / den, q1 = p[i1] / den;
        float wsum = q0 + q1 + 1e-20f;
        g_topk_idx[2 * t]     = i0;
        g_topk_idx[2 * t + 1] = i1;
        g_topk_w[2 * t]       = q0 / wsum;
        g_topk_w[2 * t + 1]   = q1 / wsum;
    }
}

// ---------------- scatter: deterministic compaction by expert --------------
__global__ void __launch_bounds__(256) scatter_kernel()
{
    int wid = threadIdx.x >> 5, lane = threadIdx.x & 31;
    __shared__ int scnt[E_DIM];

    int c = 0;
    for (int baset = 0; baset < T_DIM; baset += 32) {
        int t = baset + lane;
        bool m = (g_topk_idx[2 * t] == wid) || (g_topk_idx[2 * t + 1] == wid);
        unsigned b = __ballot_sync(0xffffffffu, m);
        c += __popc(b);
    }
    if (lane == 0) scnt[wid] = c;
    __syncthreads();
    if (threadIdx.x == 0) {
        int acc = 0;
        for (int e = 0; e < E_DIM; e++) { g_base[e] = acc; g_cnt[e] = scnt[e]; acc += scnt[e]; }
    }
    __syncthreads();

    int pos = g_base[wid];
    for (int baset = 0; baset < T_DIM; baset += 32) {
        int t = baset + lane;
        int k = -1;
        if (g_topk_idx[2 * t] == wid) k = 0;
        else if (g_topk_idx[2 * t + 1] == wid) k = 1;
        unsigned b = __ballot_sync(0xffffffffu, k >= 0);
        int off = __popc(b & ((1u << lane) - 1u));
        if (k >= 0) {
            g_tok[pos + off] = t;
            g_slot[2 * t + k] = pos + off;
        }
        pos += __popc(b);
    }
}

// ---------------- gather rows -> g_xh (half) --------------------------------
__global__ void __launch_bounds__(256) gather_kernel(const float* __restrict__ x)
{
    int p = blockIdx.x;
    int t = (p < NPAIR) ? g_tok[p] : 0;
    float4 v = ((const float4*)(x + (size_t)t * H_DIM))[threadIdx.x];
    __half2* d = (__half2*)(g_xh + (size_t)p * H_DIM);
    d[threadIdx.x * 2]     = __floats2half2_rn(v.x, v.y);
    d[threadIdx.x * 2 + 1] = __floats2half2_rn(v.z, v.w);
}

// ---------------- transpose+convert: src f32 [R][C] -> dst half [C][R] ------
__global__ void __launch_bounds__(256) convT_kernel(
    const float* __restrict__ src, __half* __restrict__ dst, int R, int C)
{
    __shared__ float t[32][33];
    size_t eoff = (size_t)blockIdx.z * R * C;
    src += eoff; dst += eoff;
    int c0 = blockIdx.x * 32, r0 = blockIdx.y * 32;
    int x = threadIdx.x, y = threadIdx.y;
#pragma unroll
    for (int i = 0; i < 32; i += 8)
        t[y + i][x] = src[(size_t)(r0 + y + i) * C + c0 + x];
    __syncthreads();
#pragma unroll
    for (int i = 0; i < 32; i += 8)
        dst[(size_t)(c0 + y + i) * R + r0 + x] = __float2half_rn(t[x][y + i]);
}

// ---------------- GEMM1: g_xh[128,1024] @ w1h -> swiglu -> g_acth -----------
// Block 128 x (128 gate + 128 up B-rows); 8 warps (2x4), warp tile 64x64.
__global__ void __launch_bounds__(256) gemm1_kernel()
{
    int e = blockIdx.z;
    int cnt = g_cnt[e];
    int m0 = blockIdx.y * 128;
    if (m0 >= cnt) return;
    int base = g_base[e];
    int n0 = blockIdx.x * 128;

    extern __shared__ char smem[];
    uint32_t sb = smem_u32(smem);
    int tid = threadIdx.x, lane = tid & 31, wid = tid >> 5;
    int wm = wid >> 2, wn = wid & 3;

    // cp.async units
    uint32_t adst[4]; const __half* asrc[4];
#pragma unroll
    for (int i = 0; i < 4; i++) {
        int idx = tid + (i << 8);
        int r = idx >> 3, c = idx & 7;
        adst[i] = (uint32_t)(r * 128 + ((c ^ (r & 7)) << 4));
        asrc[i] = g_xh + (size_t)(base + m0 + r) * H_DIM + c * 8;
    }
    uint32_t bdst[8]; const __half* bsrc[8];
    const __half* w1e = g_w1h + (size_t)e * ((size_t)FFN2_DIM * H_DIM);
#pragma unroll
    for (int i = 0; i < 8; i++) {
        int idx = tid + (i << 8);
        int r = idx >> 3, c = idx & 7;
        bdst[i] = (uint32_t)(r * 128 + ((c ^ (r & 7)) << 4));
        int jrow = (r < 128) ? (n0 + r) : (FFN_DIM + n0 + r - 128);
        bsrc[i] = w1e + (size_t)jrow * H_DIM + c * 8;
    }

    auto load_stage = [&](int t) {
        uint32_t ab = sb + (uint32_t)(t % 3) * STAGE_BYTES;
        uint32_t bb = ab + 16384u;
        int k0 = t * 64;
#pragma unroll
        for (int i = 0; i < 4; i++) cpa16(ab + adst[i], asrc[i] + k0);
#pragma unroll
        for (int i = 0; i < 8; i++) cpa16(bb + bdst[i], bsrc[i] + k0);
    };

    // fragment addressing
    uint32_t aoffr = (uint32_t)((wm * 64 + (lane & 15)) * 128);
    uint32_t rp = ((lane >> 3) & 1) * 8 + (lane & 7);
    uint32_t boffr[4];
#pragma unroll
    for (int p = 0; p < 4; p++) {
        int nb = (p < 2) ? (wn * 32 + p * 16) : (128 + wn * 32 + (p - 2) * 16);
        boffr[p] = (uint32_t)((nb + rp) * 128);
    }
    uint32_t cxb = (lane >> 4), rx = (lane & 7);

    float acc[4][8][4] = {};

    load_stage(0); CPCOMMIT();
    load_stage(1); CPCOMMIT();

    const int NS = H_DIM / 64;  // 16
    for (int s = 0; s < NS; s++) {
        CPWAIT1();
        __syncthreads();
        if (s + 2 < NS) load_stage(s + 2);
        CPCOMMIT();
        uint32_t ab = sb + (uint32_t)(s % 3) * STAGE_BYTES;
        uint32_t bb = ab + 16384u;
#pragma unroll
        for (int kk = 0; kk < 4; kk++) {
            uint32_t cx = ((((uint32_t)kk << 1) + cxb) ^ rx) << 4;
            uint32_t af[4][4], bf[4][4];
#pragma unroll
            for (int mt = 0; mt < 4; mt++) ldm4(af[mt], ab + aoffr + mt * 2048 + cx);
#pragma unroll
            for (int p = 0; p < 4; p++) ldm4(bf[p], bb + boffr[p] + cx);
#pragma unroll
            for (int mt = 0; mt < 4; mt++)
#pragma unroll
                for (int p = 0; p < 4; p++) {
                    mma16(acc[mt][2 * p],     af[mt], bf[p][0], bf[p][2]);
                    mma16(acc[mt][2 * p + 1], af[mt], bf[p][1], bf[p][3]);
                }
        }
    }

    // epilogue: swiglu, store half
    int gid = lane >> 2, tig = lane & 3;
#pragma unroll
    for (int mt = 0; mt < 4; mt++) {
        int r1 = m0 + wm * 64 + mt * 16 + gid;
#pragma unroll
        for (int j = 0; j < 4; j++) {
            int col = n0 + wn * 32 + j * 8 + tig * 2;
            float g0 = acc[mt][j][0], g1 = acc[mt][j][1];
            float u0 = acc[mt][j + 4][0], u1 = acc[mt][j + 4][1];
            if (r1 < cnt) {
                __half2 h = __floats2half2_rn(g0 * u0 / (1.f + __expf(-g0)),
                                              g1 * u1 / (1.f + __expf(-g1)));
                *(__half2*)&g_acth[(size_t)(base + r1) * FFN_DIM + col] = h;
            }
            float g2 = acc[mt][j][2], g3 = acc[mt][j][3];
            float u2 = acc[mt][j + 4][2], u3 = acc[mt][j + 4][3];
            if (r1 + 8 < cnt) {
                __half2 h = __floats2half2_rn(g2 * u2 / (1.f + __expf(-g2)),
                                              g3 * u3 / (1.f + __expf(-g3)));
                *(__half2*)&g_acth[(size_t)(base + r1 + 8) * FFN_DIM + col] = h;
            }
        }
    }
}

// ---------------- GEMM2: g_acth[128,1408] @ w2h -> g_y ----------------------
// Block 128 x 256; 8 warps (2x4), warp tile 64x64.
__global__ void __launch_bounds__(256) gemm2_kernel()
{
    int e = blockIdx.z;
    int cnt = g_cnt[e];
    int m0 = blockIdx.y * 128;
    if (m0 >= cnt) return;
    int base = g_base[e];
    int n0 = blockIdx.x * 256;

    extern __shared__ char smem[];
    uint32_t sb = smem_u32(smem);
    int tid = threadIdx.x, lane = tid & 31, wid = tid >> 5;
    int wm = wid >> 2, wn = wid & 3;

    uint32_t adst[4]; const __half* asrc[4];
#pragma unroll
    for (int i = 0; i < 4; i++) {
        int idx = tid + (i << 8);
        int r = idx >> 3, c = idx & 7;
        adst[i] = (uint32_t)(r * 128 + ((c ^ (r & 7)) << 4));
        asrc[i] = g_acth + (size_t)(base + m0 + r) * FFN_DIM + c * 8;
    }
    uint32_t bdst[8]; const __half* bsrc[8];
    const __half* w2e = g_w2h + (size_t)e * ((size_t)H_DIM * FFN_DIM);
#pragma unroll
    for (int i = 0; i < 8; i++) {
        int idx = tid + (i << 8);
        int r = idx >> 3, c = idx & 7;
        bdst[i] = (uint32_t)(r * 128 + ((c ^ (r & 7)) << 4));
        bsrc[i] = w2e + (size_t)(n0 + r) * FFN_DIM + c * 8;
    }

    auto load_stage = [&](int t) {
        uint32_t ab = sb + (uint32_t)(t % 3) * STAGE_BYTES;
        uint32_t bb = ab + 16384u;
        int k0 = t * 64;
#pragma unroll
        for (int i = 0; i < 4; i++) cpa16(ab + adst[i], asrc[i] + k0);
#pragma unroll
        for (int i = 0; i < 8; i++) cpa16(bb + bdst[i], bsrc[i] + k0);
    };

    uint32_t aoffr = (uint32_t)((wm * 64 + (lane & 15)) * 128);
    uint32_t rp = ((lane >> 3) & 1) * 8 + (lane & 7);
    uint32_t boffr[4];
#pragma unroll
    for (int p = 0; p < 4; p++)
        boffr[p] = (uint32_t)((wn * 64 + p * 16 + rp) * 128);
    uint32_t cxb = (lane >> 4), rx = (lane & 7);

    float acc[4][8][4] = {};

    load_stage(0); CPCOMMIT();
    load_stage(1); CPCOMMIT();

    const int NS = FFN_DIM / 64;  // 22
    for (int s = 0; s < NS; s++) {
        CPWAIT1();
        __syncthreads();
        if (s + 2 < NS) load_stage(s + 2);
        CPCOMMIT();
        uint32_t ab = sb + (uint32_t)(s % 3) * STAGE_BYTES;
        uint32_t bb = ab + 16384u;
#pragma unroll
        for (int kk = 0; kk < 4; kk++) {
            uint32_t cx = ((((uint32_t)kk << 1) + cxb) ^ rx) << 4;
            uint32_t af[4][4], bf[4][4];
#pragma unroll
            for (int mt = 0; mt < 4; mt++) ldm4(af[mt], ab + aoffr + mt * 2048 + cx);
#pragma unroll
            for (int p = 0; p < 4; p++) ldm4(bf[p], bb + boffr[p] + cx);
#pragma unroll
            for (int mt = 0; mt < 4; mt++)
#pragma unroll
                for (int p = 0; p < 4; p++) {
                    mma16(acc[mt][2 * p],     af[mt], bf[p][0], bf[p][2]);
                    mma16(acc[mt][2 * p + 1], af[mt], bf[p][1], bf[p][3]);
                }
        }
    }

    int gid = lane >> 2, tig = lane & 3;
#pragma unroll
    for (int mt = 0; mt < 4; mt++) {
        int r1 = m0 + wm * 64 + mt * 16 + gid;
#pragma unroll
        for (int j = 0; j < 8; j++) {
            int col = n0 + wn * 64 + j * 8 + tig * 2;
            if (r1 < cnt) {
                float2 o = make_float2(acc[mt][j][0], acc[mt][j][1]);
                *(float2*)&g_y[(size_t)(base + r1) * H_DIM + col] = o;
            }
            if (r1 + 8 < cnt) {
                float2 o = make_float2(acc[mt][j][2], acc[mt][j][3]);
                *(float2*)&g_y[(size_t)(base + r1 + 8) * H_DIM + col] = o;
            }
        }
    }
}

// ---------------- combine: out[t] = w0*Y[slot0] + w1*Y[slot1] --------------
__global__ void __launch_bounds__(256) combine_kernel(float* __restrict__ out)
{
    int t = blockIdx.x;
    int s0 = g_slot[2 * t], s1 = g_slot[2 * t + 1];
    float w0 = g_topk_w[2 * t], w1 = g_topk_w[2 * t + 1];
    const float* y0 = g_y + (size_t)s0 * H_DIM;
    const float* y1 = g_y + (size_t)s1 * H_DIM;
    float* orow = out + (size_t)t * H_DIM;

    int h = threadIdx.x * 4;
    float4 a = *(const float4*)(y0 + h);
    float4 b = *(const float4*)(y1 + h);
    float4 o;
    o.x = w0 * a.x + w1 * b.x;
    o.y = w0 * a.y + w1 * b.y;
    o.z = w0 * a.z + w1 * b.z;
    o.w = w0 * a.w + w1 * b.w;
    *(float4*)(orow + h) = o;
}

// ---------------- launch ----------------------------------------------------
extern "C" void kernel_launch(void* const* d_in, const int* in_sizes, int n_in,
                              void* d_out, int out_size)
{
    const float* hidden = (const float*)d_in[0];   // [S, B, H] == [T, H]
    const float* gate_w = (const float*)d_in[1];   // [E, H]
    const float* w1     = (const float*)d_in[2];   // [E, H, 2*FFN]
    const float* w2     = (const float*)d_in[3];   // [E, FFN, H]
    float* out          = (float*)d_out;

    cudaFuncSetAttribute(gemm1_kernel, cudaFuncAttributeMaxDynamicSharedMemorySize, SMEM_BYTES);
    cudaFuncSetAttribute(gemm2_kernel, cudaFuncAttributeMaxDynamicSharedMemorySize, SMEM_BYTES);

    gate_kernel<<<T_DIM, 256>>>(hidden, gate_w);
    scatter_kernel<<<1, 256>>>();
    __half* w1h; cudaGetSymbolAddress((void**)&w1h, g_w1h);
    __half* w2h; cudaGetSymbolAddress((void**)&w2h, g_w2h);
    convT_kernel<<<dim3(FFN2_DIM / 32, H_DIM / 32, E_DIM), dim3(32, 8)>>>(
        w1, w1h, H_DIM, FFN2_DIM);
    convT_kernel<<<dim3(H_DIM / 32, FFN_DIM / 32, E_DIM), dim3(32, 8)>>>(
        w2, w2h, FFN_DIM, H_DIM);
    gather_kernel<<<NPAD, 256>>>(hidden);
    gemm1_kernel<<<dim3(FFN_DIM / 128, NPAIR / 128, E_DIM), 256, SMEM_BYTES>>>();
    gemm2_kernel<<<dim3(H_DIM / 256, NPAIR / 128, E_DIM), 256, SMEM_BYTES>>>();
    combine_kernel<<<T_DIM, 256>>>(out);
}

// round 5
// speedup vs baseline: 4.9784x; 1.5857x over previous
#include <cuda_runtime.h>
#include <cuda_fp16.h>
#include <cstdint>

// Problem shapes (fixed by the dataset)
#define T_DIM 2048
#define H_DIM 1024
#define E_DIM 8
#define FFN_DIM 1408
#define FFN2_DIM 2816
#define NPAIR 4096
#define NPAD (NPAIR + 128)

// ---------------- scratch (device globals) ----------------------------------
__device__ int   g_topk_idx[T_DIM * 2];
__device__ float g_topk_w[T_DIM * 2];
__device__ int   g_tok[NPAIR];
__device__ int   g_slot[T_DIM * 2];
__device__ int   g_base[E_DIM];
__device__ int   g_cnt[E_DIM];
__device__ __align__(16) __half g_xh[(size_t)NPAD * H_DIM];                // gathered tokens (half)
__device__ __align__(16) __half g_acth[(size_t)NPAD * FFN_DIM];            // swiglu out (half)
__device__ __align__(16) float  g_y[(size_t)NPAIR * H_DIM];                // expert outputs
__device__ __align__(16) __half g_w1h[(size_t)E_DIM * H_DIM * FFN2_DIM];   // w1 half (native [k][n])
__device__ __align__(16) __half g_w2h[(size_t)E_DIM * FFN_DIM * H_DIM];    // w2 half (native [k][n])

// ---------------- helpers ----------------------------------------------------
__device__ __forceinline__ uint32_t smem_u32(const void* p) {
    uint32_t a;
    asm("{ .reg .u64 t; cvta.to.shared.u64 t, %1; cvt.u32.u64 %0, t; }"
        : "=r"(a) : "l"(p));
    return a;
}
__device__ __forceinline__ void cpa16(uint32_t dst, const void* src) {
    asm volatile("cp.async.cg.shared.global [%0], [%1], 16;" :: "r"(dst), "l"(src));
}
#define CPCOMMIT() asm volatile("cp.async.commit_group;" ::: "memory")
#define CPWAIT2()  asm volatile("cp.async.wait_group 2;" ::: "memory")

__device__ __forceinline__ void ldm4(uint32_t* f, uint32_t a) {
    asm volatile("ldmatrix.sync.aligned.m8n8.x4.shared.b16 {%0,%1,%2,%3}, [%4];"
                 : "=r"(f[0]), "=r"(f[1]), "=r"(f[2]), "=r"(f[3]) : "r"(a));
}
__device__ __forceinline__ void ldm4t(uint32_t* f, uint32_t a) {
    asm volatile("ldmatrix.sync.aligned.m8n8.x4.trans.shared.b16 {%0,%1,%2,%3}, [%4];"
                 : "=r"(f[0]), "=r"(f[1]), "=r"(f[2]), "=r"(f[3]) : "r"(a));
}
__device__ __forceinline__ void mma16(float* c, const uint32_t* a,
                                      uint32_t b0, uint32_t b1) {
    asm volatile(
        "mma.sync.aligned.m16n8k16.row.col.f32.f16.f16.f32 "
        "{%0,%1,%2,%3}, {%4,%5,%6,%7}, {%8,%9}, {%0,%1,%2,%3};"
        : "+f"(c[0]), "+f"(c[1]), "+f"(c[2]), "+f"(c[3])
        : "r"(a[0]), "r"(a[1]), "r"(a[2]), "r"(a[3]), "r"(b0), "r"(b1));
}

// stage: A [128 m][64 k] half = 16KB at +0 ; B [64 k][256 n] half = 32KB at +16384
#define STAGE_BYTES 49152u
#define NSTAGE 4
#define SMEM_BYTES (NSTAGE * STAGE_BYTES)   // 196608

// ---------------- gate: softmax(x @ gate_w^T), top-2, renormalize ----------
__global__ void __launch_bounds__(256) gate_kernel(
    const float* __restrict__ x, const float* __restrict__ gw)
{
    int t = blockIdx.x;
    const float* xr = x + (size_t)t * H_DIM;
    int wid = threadIdx.x >> 5, lane = threadIdx.x & 31;
    __shared__ float sc[E_DIM];

    const float* g = gw + (size_t)wid * H_DIM;
    float s = 0.f;
    for (int i = lane; i < H_DIM; i += 32) s += xr[i] * g[i];
#pragma unroll
    for (int o = 16; o; o >>= 1) s += __shfl_xor_sync(0xffffffffu, s, o);
    if (lane == 0) sc[wid] = s;
    __syncthreads();

    if (threadIdx.x == 0) {
        float m = -1e30f;
#pragma unroll
        for (int e = 0; e < E_DIM; e++) m = fmaxf(m, sc[e]);
        float p[E_DIM], den = 0.f;
#pragma unroll
        for (int e = 0; e < E_DIM; e++) { p[e] = __expf(sc[e] - m); den += p[e]; }
        int i0 = 0;
#pragma unroll
        for (int e = 1; e < E_DIM; e++) if (p[e] > p[i0]) i0 = e;
        int i1 = -1;
#pragma unroll
        for (int e = 0; e < E_DIM; e++)
            if (e != i0 && (i1 < 0 || p[e] > p[i1])) i1 = e;
        float q0 = p[i0] / den, q1 = p[i1] / den;
        float wsum = q0 + q1 + 1e-20f;
        g_topk_idx[2 * t]     = i0;
        g_topk_idx[2 * t + 1] = i1;
        g_topk_w[2 * t]       = q0 / wsum;
        g_topk_w[2 * t + 1]   = q1 / wsum;
    }
}

// ---------------- scatter: deterministic compaction by expert --------------
__global__ void __launch_bounds__(256) scatter_kernel()
{
    int wid = threadIdx.x >> 5, lane = threadIdx.x & 31;
    __shared__ int scnt[E_DIM];

    int c = 0;
    for (int baset = 0; baset < T_DIM; baset += 32) {
        int t = baset + lane;
        bool m = (g_topk_idx[2 * t] == wid) || (g_topk_idx[2 * t + 1] == wid);
        unsigned b = __ballot_sync(0xffffffffu, m);
        c += __popc(b);
    }
    if (lane == 0) scnt[wid] = c;
    __syncthreads();
    if (threadIdx.x == 0) {
        int acc = 0;
        for (int e = 0; e < E_DIM; e++) { g_base[e] = acc; g_cnt[e] = scnt[e]; acc += scnt[e]; }
    }
    __syncthreads();

    int pos = g_base[wid];
    for (int baset = 0; baset < T_DIM; baset += 32) {
        int t = baset + lane;
        int k = -1;
        if (g_topk_idx[2 * t] == wid) k = 0;
        else if (g_topk_idx[2 * t + 1] == wid) k = 1;
        unsigned b = __ballot_sync(0xffffffffu, k >= 0);
        int off = __popc(b & ((1u << lane) - 1u));
        if (k >= 0) {
            g_tok[pos + off] = t;
            g_slot[2 * t + k] = pos + off;
        }
        pos += __popc(b);
    }
}

// ---------------- gather rows -> g_xh (half) --------------------------------
__global__ void __launch_bounds__(256) gather_kernel(const float* __restrict__ x)
{
    int p = blockIdx.x;
    int t = (p < NPAIR) ? g_tok[p] : 0;
    float4 v = ((const float4*)(x + (size_t)t * H_DIM))[threadIdx.x];
    __half2* d = (__half2*)(g_xh + (size_t)p * H_DIM);
    d[threadIdx.x * 2]     = __floats2half2_rn(v.x, v.y);
    d[threadIdx.x * 2 + 1] = __floats2half2_rn(v.z, v.w);
}

// ---------------- streaming f32 -> f16 cast (no transpose) ------------------
__global__ void __launch_bounds__(256) convW_kernel(
    const float* __restrict__ src, __half* __restrict__ dst, size_t n4)
{
    size_t i = (size_t)blockIdx.x * blockDim.x + threadIdx.x;
    size_t stride = (size_t)gridDim.x * blockDim.x;
    for (; i < n4; i += stride) {
        float4 v = ((const float4*)src)[i];
        __half2 h0 = __floats2half2_rn(v.x, v.y);
        __half2 h1 = __floats2half2_rn(v.z, v.w);
        uint2 o = make_uint2(*(uint32_t*)&h0, *(uint32_t*)&h1);
        ((uint2*)dst)[i] = o;
    }
}

// ---------------- GEMM1: g_xh[128,1024] @ w1h([k][n]) -> swiglu -> g_acth ---
// CTA: 128 M x 128 FFN cols; B stage [64k][256n] (gate cols 0-127, up 128-255).
// 8 warps (2m x 4n), warp tile 64 x 64 (32 gate + 32 up FFN cols).
__global__ void __launch_bounds__(256) gemm1_kernel()
{
    int e = blockIdx.z;
    int cnt = g_cnt[e];
    int m0 = blockIdx.y * 128;
    if (m0 >= cnt) return;
    int base = g_base[e];
    int n0 = blockIdx.x * 128;

    extern __shared__ char smem[];
    uint32_t sb = smem_u32(smem);
    int tid = threadIdx.x, lane = tid & 31, wid = tid >> 5;
    int wm = wid >> 2, wn = wid & 3;

    // A cp.async: 4 units/thread; A[r][c*8..], swizzled 128B pitch
    uint32_t adst[4]; const __half* asrc[4];
#pragma unroll
    for (int i = 0; i < 4; i++) {
        int idx = tid + (i << 8);
        int r = idx >> 3, c = idx & 7;
        adst[i] = (uint32_t)(r * 128 + ((c ^ (r & 7)) << 4));
        asrc[i] = g_xh + (size_t)(base + m0 + r) * H_DIM + c * 8;
    }
    // B cp.async: 8 units/thread; B[k=r][unit c of 32], 512B pitch, swizzle low3
    uint32_t bdst[8]; const __half* bsrc[8];
    const __half* w1e = g_w1h + (size_t)e * ((size_t)H_DIM * FFN2_DIM);
#pragma unroll
    for (int i = 0; i < 8; i++) {
        int idx = tid + (i << 8);
        int r = idx >> 5, c = idx & 31;
        bdst[i] = (uint32_t)(r * 512 + ((((c & 24) | ((c ^ r) & 7))) << 4));
        int col = (c < 16) ? (n0 + c * 8) : (FFN_DIM + n0 + (c - 16) * 8);
        bsrc[i] = w1e + (size_t)r * FFN2_DIM + col;
    }

    auto load_stage = [&](int t) {
        uint32_t ab = sb + (uint32_t)(t & 3) * STAGE_BYTES;
        uint32_t bb = ab + 16384u;
        int k0 = t * 64;
#pragma unroll
        for (int i = 0; i < 4; i++) cpa16(ab + adst[i], asrc[i] + k0);
#pragma unroll
        for (int i = 0; i < 8; i++) cpa16(bb + bdst[i], bsrc[i] + (size_t)k0 * FFN2_DIM);
    };

    // fragment addressing
    uint32_t aoffr = (uint32_t)((wm * 64 + (lane & 15)) * 128);
    uint32_t cxb = (uint32_t)(lane >> 4), rx = (uint32_t)(lane & 7);
    // B (trans): lane -> k_local row + n-unit; swizzle fixed per lane
    uint32_t klocal = ((lane >> 3) & 1) * 8 + (lane & 7);
    uint32_t bbase[4];
#pragma unroll
    for (int p = 0; p < 4; p++) {
        uint32_t u = (p < 2) ? (uint32_t)(wn * 4 + p * 2)
                             : (uint32_t)(16 + wn * 4 + (p - 2) * 2);
        uint32_t unit = u + (uint32_t)(lane >> 4);
        uint32_t usw = (unit & 24) | ((unit ^ (lane & 7)) & 7);
        bbase[p] = klocal * 512 + (usw << 4);
    }

    float acc[4][8][4] = {};

    load_stage(0); CPCOMMIT();
    load_stage(1); CPCOMMIT();
    load_stage(2); CPCOMMIT();

    const int NS = H_DIM / 64;  // 16
    for (int s = 0; s < NS; s++) {
        CPWAIT2();
        __syncthreads();
        if (s + 3 < NS) load_stage(s + 3);
        CPCOMMIT();
        uint32_t ab = sb + (uint32_t)(s & 3) * STAGE_BYTES;
        uint32_t bb = ab + 16384u;
#pragma unroll
        for (int kk = 0; kk < 4; kk++) {
            uint32_t cx = ((((uint32_t)kk << 1) + cxb) ^ rx) << 4;
            uint32_t af[4][4], bf[4][4];
#pragma unroll
            for (int mt = 0; mt < 4; mt++) ldm4(af[mt], ab + aoffr + mt * 2048 + cx);
#pragma unroll
            for (int p = 0; p < 4; p++) ldm4t(bf[p], bb + bbase[p] + (uint32_t)kk * 8192);
#pragma unroll
            for (int mt = 0; mt < 4; mt++)
#pragma unroll
                for (int p = 0; p < 4; p++) {
                    mma16(acc[mt][2 * p],     af[mt], bf[p][0], bf[p][1]);
                    mma16(acc[mt][2 * p + 1], af[mt], bf[p][2], bf[p][3]);
                }
        }
    }

    // epilogue: swiglu, store half
    int gid = lane >> 2, tig = lane & 3;
#pragma unroll
    for (int mt = 0; mt < 4; mt++) {
        int r1 = m0 + wm * 64 + mt * 16 + gid;
#pragma unroll
        for (int j = 0; j < 4; j++) {
            int col = n0 + wn * 32 + j * 8 + tig * 2;
            float g0 = acc[mt][j][0], g1 = acc[mt][j][1];
            float u0 = acc[mt][j + 4][0], u1 = acc[mt][j + 4][1];
            if (r1 < cnt) {
                __half2 h = __floats2half2_rn(g0 * u0 / (1.f + __expf(-g0)),
                                              g1 * u1 / (1.f + __expf(-g1)));
                *(__half2*)&g_acth[(size_t)(base + r1) * FFN_DIM + col] = h;
            }
            float g2 = acc[mt][j][2], g3 = acc[mt][j][3];
            float u2 = acc[mt][j + 4][2], u3 = acc[mt][j + 4][3];
            if (r1 + 8 < cnt) {
                __half2 h = __floats2half2_rn(g2 * u2 / (1.f + __expf(-g2)),
                                              g3 * u3 / (1.f + __expf(-g3)));
                *(__half2*)&g_acth[(size_t)(base + r1 + 8) * FFN_DIM + col] = h;
            }
        }
    }
}

// ---------------- GEMM2: g_acth[128,1408] @ w2h([k][n]) -> g_y --------------
// CTA: 128 M x 256 N; 8 warps (2m x 4n), warp tile 64x64.
__global__ void __launch_bounds__(256) gemm2_kernel()
{
    int e = blockIdx.z;
    int cnt = g_cnt[e];
    int m0 = blockIdx.y * 128;
    if (m0 >= cnt) return;
    int base = g_base[e];
    int n0 = blockIdx.x * 256;

    extern __shared__ char smem[];
    uint32_t sb = smem_u32(smem);
    int tid = threadIdx.x, lane = tid & 31, wid = tid >> 5;
    int wm = wid >> 2, wn = wid & 3;

    uint32_t adst[4]; const __half* asrc[4];
#pragma unroll
    for (int i = 0; i < 4; i++) {
        int idx = tid + (i << 8);
        int r = idx >> 3, c = idx & 7;
        adst[i] = (uint32_t)(r * 128 + ((c ^ (r & 7)) << 4));
        asrc[i] = g_acth + (size_t)(base + m0 + r) * FFN_DIM + c * 8;
    }
    uint32_t bdst[8]; const __half* bsrc[8];
    const __half* w2e = g_w2h + (size_t)e * ((size_t)FFN_DIM * H_DIM);
#pragma unroll
    for (int i = 0; i < 8; i++) {
        int idx = tid + (i << 8);
        int r = idx >> 5, c = idx & 31;
        bdst[i] = (uint32_t)(r * 512 + ((((c & 24) | ((c ^ r) & 7))) << 4));
        bsrc[i] = w2e + (size_t)r * H_DIM + n0 + c * 8;
    }

    auto load_stage = [&](int t) {
        uint32_t ab = sb + (uint32_t)(t & 3) * STAGE_BYTES;
        uint32_t bb = ab + 16384u;
        int k0 = t * 64;
#pragma unroll
        for (int i = 0; i < 4; i++) cpa16(ab + adst[i], asrc[i] + k0);
#pragma unroll
        for (int i = 0; i < 8; i++) cpa16(bb + bdst[i], bsrc[i] + (size_t)k0 * H_DIM);
    };

    uint32_t aoffr = (uint32_t)((wm * 64 + (lane & 15)) * 128);
    uint32_t cxb = (uint32_t)(lane >> 4), rx = (uint32_t)(lane & 7);
    uint32_t klocal = ((lane >> 3) & 1) * 8 + (lane & 7);
    uint32_t bbase[4];
#pragma unroll
    for (int p = 0; p < 4; p++) {
        uint32_t unit = (uint32_t)(wn * 8 + p * 2) + (uint32_t)(lane >> 4);
        uint32_t usw = (unit & 24) | ((unit ^ (lane & 7)) & 7);
        bbase[p] = klocal * 512 + (usw << 4);
    }

    float acc[4][8][4] = {};

    load_stage(0); CPCOMMIT();
    load_stage(1); CPCOMMIT();
    load_stage(2); CPCOMMIT();

    const int NS = FFN_DIM / 64;  // 22
    for (int s = 0; s < NS; s++) {
        CPWAIT2();
        __syncthreads();
        if (s + 3 < NS) load_stage(s + 3);
        CPCOMMIT();
        uint32_t ab = sb + (uint32_t)(s & 3) * STAGE_BYTES;
        uint32_t bb = ab + 16384u;
#pragma unroll
        for (int kk = 0; kk < 4; kk++) {
            uint32_t cx = ((((uint32_t)kk << 1) + cxb) ^ rx) << 4;
            uint32_t af[4][4], bf[4][4];
#pragma unroll
            for (int mt = 0; mt < 4; mt++) ldm4(af[mt], ab + aoffr + mt * 2048 + cx);
#pragma unroll
            for (int p = 0; p < 4; p++) ldm4t(bf[p], bb + bbase[p] + (uint32_t)kk * 8192);
#pragma unroll
            for (int mt = 0; mt < 4; mt++)
#pragma unroll
                for (int p = 0; p < 4; p++) {
                    mma16(acc[mt][2 * p],     af[mt], bf[p][0], bf[p][1]);
                    mma16(acc[mt][2 * p + 1], af[mt], bf[p][2], bf[p][3]);
                }
        }
    }

    int gid = lane >> 2, tig = lane & 3;
#pragma unroll
    for (int mt = 0; mt < 4; mt++) {
        int r1 = m0 + wm * 64 + mt * 16 + gid;
#pragma unroll
        for (int j = 0; j < 8; j++) {
            int col = n0 + wn * 64 + j * 8 + tig * 2;
            if (r1 < cnt) {
                float2 o = make_float2(acc[mt][j][0], acc[mt][j][1]);
                *(float2*)&g_y[(size_t)(base + r1) * H_DIM + col] = o;
            }
            if (r1 + 8 < cnt) {
                float2 o = make_float2(acc[mt][j][2], acc[mt][j][3]);
                *(float2*)&g_y[(size_t)(base + r1 + 8) * H_DIM + col] = o;
            }
        }
    }
}

// ---------------- combine: out[t] = w0*Y[slot0] + w1*Y[slot1] --------------
__global__ void __launch_bounds__(256) combine_kernel(float* __restrict__ out)
{
    int t = blockIdx.x;
    int s0 = g_slot[2 * t], s1 = g_slot[2 * t + 1];
    float w0 = g_topk_w[2 * t], w1 = g_topk_w[2 * t + 1];
    const float* y0 = g_y + (size_t)s0 * H_DIM;
    const float* y1 = g_y + (size_t)s1 * H_DIM;
    float* orow = out + (size_t)t * H_DIM;

    int h = threadIdx.x * 4;
    float4 a = *(const float4*)(y0 + h);
    float4 b = *(const float4*)(y1 + h);
    float4 o;
    o.x = w0 * a.x + w1 * b.x;
    o.y = w0 * a.y + w1 * b.y;
    o.z = w0 * a.z + w1 * b.z;
    o.w = w0 * a.w + w1 * b.w;
    *(float4*)(orow + h) = o;
}

// ---------------- launch ----------------------------------------------------
extern "C" void kernel_launch(void* const* d_in, const int* in_sizes, int n_in,
                              void* d_out, int out_size)
{
    const float* hidden = (const float*)d_in[0];   // [S, B, H] == [T, H]
    const float* gate_w = (const float*)d_in[1];   // [E, H]
    const float* w1     = (const float*)d_in[2];   // [E, H, 2*FFN]
    const float* w2     = (const float*)d_in[3];   // [E, FFN, H]
    float* out          = (float*)d_out;

    cudaFuncSetAttribute(gemm1_kernel, cudaFuncAttributeMaxDynamicSharedMemorySize, SMEM_BYTES);
    cudaFuncSetAttribute(gemm2_kernel, cudaFuncAttributeMaxDynamicSharedMemorySize, SMEM_BYTES);

    gate_kernel<<<T_DIM, 256>>>(hidden, gate_w);
    scatter_kernel<<<1, 256>>>();
    __half* w1h; cudaGetSymbolAddress((void**)&w1h, g_w1h);
    __half* w2h; cudaGetSymbolAddress((void**)&w2h, g_w2h);
    convW_kernel<<<2048, 256>>>(w1, w1h, (size_t)E_DIM * H_DIM * FFN2_DIM / 4);
    convW_kernel<<<2048, 256>>>(w2, w2h, (size_t)E_DIM * FFN_DIM * H_DIM / 4);
    gather_kernel<<<NPAD, 256>>>(hidden);
    gemm1_kernel<<<dim3(FFN_DIM / 128, NPAIR / 128, E_DIM), 256, SMEM_BYTES>>>();
    gemm2_kernel<<<dim3(H_DIM / 256, NPAIR / 128, E_DIM), 256, SMEM_BYTES>>>();
    combine_kernel<<<T_DIM, 256>>>(out);
}